// round 8
// baseline (speedup 1.0000x reference)
#include <cuda_runtime.h>

// rgb: (1, 3, 2048, 2048) fp32; num_bins=4, kernel_size=3, pixel_size=32
#define H       2048
#define W       2048
#define PS      32
#define OB      (H / PS)        // 64
#define NB      4
#define PLANE   (H * W)
#define NCELL   (OB * OB)       // 4096

// ---------------------------------------------------------------------------
// Fused, 2 warps per cell (cell x 16-row half), stores via __stcg (L1-bypass,
// L2-cached) to test/relieve the L1 write-through port. Structure identical
// to the R7 kernel (11.04us, at the measured write-path floor).
// ---------------------------------------------------------------------------
__global__ __launch_bounds__(256)
void pixel_effect_fused(const float* __restrict__ rgb, float* __restrict__ out) {
    const int gwarp = blockIdx.x * 8 + (threadIdx.x >> 5);  // 0 .. 8191
    const int lane  = threadIdx.x & 31;
    const int cell  = gwarp >> 1;        // 0 .. 4095
    const int half  = gwarp & 1;         // 16-row half 0/1
    const int ow = cell & (OB - 1);
    const int oh = cell >> 6;

    float r = 0.f, g = 0.f, b = 0.f;
    int bin = -1;

    if (lane < 9) {
        const int dh = lane / 3 - 1;
        const int dw = lane - (lane / 3) * 3 - 1;
        const int h = oh * PS + dh;
        const int w = ow * PS + dw;
        if (h >= 0 && w >= 0) {          // high edge never OOB (max center 2016)
            const float* p = rgb + (size_t)h * W + w;
            r = __ldg(p);
            g = __ldg(p + PLANE);
            b = __ldg(p + 2 * PLANE);
            // bin = int( ((r+g+b)/3) / 256 * 4 ), IEEE ops to match JAX exactly
            const float s    = __fadd_rn(__fadd_rn(r, g), b);
            const float mean = __fdiv_rn(s, 3.0f);
            const float v    = __fmul_rn(__fdiv_rn(mean, 256.0f), 4.0f);
            bin = (int)v;
            if (bin > NB - 1) bin = NB - 1;
        }
    }

    // exact per-bin counts (uniform across warp)
    const int c0 = __popc(__ballot_sync(0xFFFFFFFFu, bin == 0));
    const int c1 = __popc(__ballot_sync(0xFFFFFFFFu, bin == 1));
    const int c2 = __popc(__ballot_sync(0xFFFFFFFFu, bin == 2));
    const int c3 = __popc(__ballot_sync(0xFFFFFFFFu, bin == 3));

    // argmax, first-max tie-break (matches jnp.argmax)
    int best = 0, bc = c0;
    if (c1 > bc) { best = 1; bc = c1; }
    if (c2 > bc) { best = 2; bc = c2; }
    if (c3 > bc) { best = 3; bc = c3; }

    // butterfly reduce: all lanes end with the winning bin's sums
    float rs = (bin == best) ? r : 0.f;
    float gs = (bin == best) ? g : 0.f;
    float bs = (bin == best) ? b : 0.f;
    #pragma unroll
    for (int off = 16; off > 0; off >>= 1) {
        rs += __shfl_xor_sync(0xFFFFFFFFu, rs, off);
        gs += __shfl_xor_sync(0xFFFFFFFFu, gs, off);
        bs += __shfl_xor_sync(0xFFFFFFFFu, bs, off);
    }

    const float imax = (float)bc;                 // uniform
    const float cr = __fdiv_rn(rs, imax);
    const float cg = __fdiv_rn(gs, imax);
    const float cb = __fdiv_rn(bs, imax);

    const float4 vr = make_float4(cr, cr, cr, cr);
    const float4 vg = make_float4(cg, cg, cg, cg);
    const float4 vb = make_float4(cb, cb, cb, cb);

    // half fill: lane -> col4 = lane&7, rows half*16 + (lane>>3)*4 + {0..3}
    const int c4    = lane & 7;
    const int rbase = half * 16 + (lane >> 3) * 4;
    const size_t base = (size_t)(oh * PS + rbase) * W + (size_t)ow * PS + (size_t)c4 * 4;

    float* p0 = out + base;
    #pragma unroll
    for (int i = 0; i < 4; i++) {
        float* p = p0 + (size_t)i * W;
        __stcg(reinterpret_cast<float4*>(p),                     vr);
        __stcg(reinterpret_cast<float4*>(p + (size_t)PLANE),     vg);
        __stcg(reinterpret_cast<float4*>(p + (size_t)2 * PLANE), vb);
    }
}

extern "C" void kernel_launch(void* const* d_in, const int* in_sizes, int n_in,
                              void* d_out, int out_size) {
    const float* rgb = (const float*)d_in[0];
    float* out = (float*)d_out;
    pixel_effect_fused<<<NCELL * 2 / 8, 256>>>(rgb, out);
}

// round 9
// speedup vs baseline: 1.0286x; 1.0286x over previous
#include <cuda_runtime.h>

// rgb: (1, 3, 2048, 2048) fp32; num_bins=4, kernel_size=3, pixel_size=32
#define H       2048
#define W       2048
#define PS      32
#define OB      (H / PS)        // 64
#define NB      4
#define PLANE   (H * W)
#define NCELL   (OB * OB)       // 4096

// 256-bit store: 8 identical floats to a 32B-aligned address (sm_100a).
__device__ __forceinline__ void st256(float* p, float v) {
    asm volatile(
        "st.global.v8.f32 [%0], {%1,%1,%1,%1,%1,%1,%1,%1};"
        :: "l"(p), "f"(v) : "memory");
}

// ---------------------------------------------------------------------------
// Fused, 2 warps per cell (cell x 16-row half). Same structure as the best
// kernel (R7, 11.04us) but stores are 256-bit st.global.v8.f32: half the STG
// instruction count for the same bytes -> tests the STG issue-cost floor.
// Lane mapping per store op: lane -> row (lane>>2), 32B-column (lane&3);
// one warp store op covers 8 rows x 128B = 1024B, fully coalesced.
// Per warp: 2 row-groups x 3 channels = 6 stores/lane.
// ---------------------------------------------------------------------------
__global__ __launch_bounds__(256)
void pixel_effect_fused(const float* __restrict__ rgb, float* __restrict__ out) {
    const int gwarp = blockIdx.x * 8 + (threadIdx.x >> 5);  // 0 .. 8191
    const int lane  = threadIdx.x & 31;
    const int cell  = gwarp >> 1;        // 0 .. 4095
    const int half  = gwarp & 1;         // 16-row half 0/1
    const int ow = cell & (OB - 1);
    const int oh = cell >> 6;

    float r = 0.f, g = 0.f, b = 0.f;
    int bin = -1;

    if (lane < 9) {
        const int dh = lane / 3 - 1;
        const int dw = lane - (lane / 3) * 3 - 1;
        const int h = oh * PS + dh;
        const int w = ow * PS + dw;
        if (h >= 0 && w >= 0) {          // high edge never OOB (max center 2016)
            const float* p = rgb + (size_t)h * W + w;
            r = __ldg(p);
            g = __ldg(p + PLANE);
            b = __ldg(p + 2 * PLANE);
            // bin = int( ((r+g+b)/3) / 256 * 4 ), IEEE ops to match JAX exactly
            const float s    = __fadd_rn(__fadd_rn(r, g), b);
            const float mean = __fdiv_rn(s, 3.0f);
            const float v    = __fmul_rn(__fdiv_rn(mean, 256.0f), 4.0f);
            bin = (int)v;
            if (bin > NB - 1) bin = NB - 1;
        }
    }

    // exact per-bin counts (uniform across warp)
    const int c0 = __popc(__ballot_sync(0xFFFFFFFFu, bin == 0));
    const int c1 = __popc(__ballot_sync(0xFFFFFFFFu, bin == 1));
    const int c2 = __popc(__ballot_sync(0xFFFFFFFFu, bin == 2));
    const int c3 = __popc(__ballot_sync(0xFFFFFFFFu, bin == 3));

    // argmax, first-max tie-break (matches jnp.argmax)
    int best = 0, bc = c0;
    if (c1 > bc) { best = 1; bc = c1; }
    if (c2 > bc) { best = 2; bc = c2; }
    if (c3 > bc) { best = 3; bc = c3; }

    // butterfly reduce: all lanes end with the winning bin's sums
    float rs = (bin == best) ? r : 0.f;
    float gs = (bin == best) ? g : 0.f;
    float bs = (bin == best) ? b : 0.f;
    #pragma unroll
    for (int off = 16; off > 0; off >>= 1) {
        rs += __shfl_xor_sync(0xFFFFFFFFu, rs, off);
        gs += __shfl_xor_sync(0xFFFFFFFFu, gs, off);
        bs += __shfl_xor_sync(0xFFFFFFFFu, bs, off);
    }

    const float imax = (float)bc;                 // uniform
    const float cr = __fdiv_rn(rs, imax);
    const float cg = __fdiv_rn(gs, imax);
    const float cb = __fdiv_rn(bs, imax);

    // half fill with 256-bit stores:
    //   lane -> rowsub = lane>>2 (0..7), col8 = lane&3 (32B units)
    //   row-groups rg=0,1 cover rows half*16 + rg*8 + rowsub
    const int rowsub = lane >> 2;
    const int col8   = lane & 3;

    #pragma unroll
    for (int rg = 0; rg < 2; rg++) {
        const int row = oh * PS + half * 16 + rg * 8 + rowsub;
        float* p = out + (size_t)row * W + (size_t)ow * PS + (size_t)col8 * 8;
        st256(p,                      cr);
        st256(p + (size_t)PLANE,      cg);
        st256(p + (size_t)2 * PLANE,  cb);
    }
}

extern "C" void kernel_launch(void* const* d_in, const int* in_sizes, int n_in,
                              void* d_out, int out_size) {
    const float* rgb = (const float*)d_in[0];
    float* out = (float*)d_out;
    pixel_effect_fused<<<NCELL * 2 / 8, 256>>>(rgb, out);
}